// round 1
// baseline (speedup 1.0000x reference)
#include <cuda_runtime.h>
#include <math.h>

// ---------------------------------------------------------------------------
// Problem constants
// ---------------------------------------------------------------------------
#define BB    2
#define TT    32
#define LLE   64
#define DD    1024
#define HH    16
#define HD    64
#define NWIN  8      // B * (T/WS)
#define SSQ   512    // WS * L
#define AROWS 4096   // NWIN * SSQ
#define TLTOK 2048   // T * L
#define BTLR  4096   // B * T * L
#define DG    2048   // 2*D
#define K3D   3072   // 3*D

// ---------------------------------------------------------------------------
// Scratch (static device globals — no allocations allowed)
// ---------------------------------------------------------------------------
__device__ float g_Q[NWIN * HH * SSQ * HD];
__device__ float g_K[NWIN * HH * SSQ * HD];
__device__ float g_V[NWIN * HH * SSQ * HD];
__device__ float g_O[(size_t)AROWS * DD];
__device__ float g_feats[(size_t)3 * BTLR * DD];
__device__ float g_G[(size_t)BTLR * DG];

__device__ __forceinline__ float gelu_f(float x) {
    return 0.5f * x * (1.0f + erff(x * 0.70710678118654752440f));
}

// ---------------------------------------------------------------------------
// Generic 128x128x8 double-buffered SGEMM, 256 threads, 8x8 microtile.
// MODE 0: QKV projection.  A = roll-gathered modality [B,T,L,D] rows.
//         C scatter -> g_Q/g_K/g_V in [NWIN][H][S][HD] layout (+bias).
// MODE 1: out projection.  A = g_O rows. Epilogue: +bias, +residual (gathered
//         at rolled-back location), write feats[which] in [B][T*L][D].
// MODE 2: gate MLP layer 1. A = concat(feats) gathered per-k. Epilogue:
//         gelu(x+bias) -> g_G.
// ---------------------------------------------------------------------------
template<int MODE>
__device__ __forceinline__ float4 gemm_loadA(const float* __restrict__ arow,
                                             int m0, int ra, int ka, int k0)
{
    if (MODE == 2) {
        int kk = k0 + ka;
        return *(const float4*)(g_feats
              + (((size_t)(kk >> 10) * BTLR + (size_t)(m0 + ra)) << 10)
              + (kk & 1023));
    } else {
        return *(const float4*)(arow + k0 + ka);
    }
}

template<int MODE>
__global__ __launch_bounds__(256) void gemm_k(
    const float* __restrict__ A0,     // MODE0: modality src; else unused
    const float* __restrict__ Bm,     // weight [K][N] row-major
    const float* __restrict__ bias,   // [N]
    const float* __restrict__ resid,  // MODE1: modality src for residual
    int which, int K, int N)
{
    __shared__ float As[2][8][132];
    __shared__ float Bs[2][8][132];

    const int tid = threadIdx.x;
    const int tx = tid & 15, ty = tid >> 4;
    const int m0 = blockIdx.y << 7, n0 = blockIdx.x << 7;

    const int ra = tid >> 1;           // A-load row in tile (0..127)
    const int ka = (tid & 1) << 2;     // A-load k offset (0 or 4)
    const int kb = tid >> 5;           // B-load k row (0..7)
    const int nb = (tid & 31) << 2;    // B-load n offset

    const float* arow = nullptr;
    if (MODE == 0) {
        int r = m0 + ra;
        int bw = r >> 9, s = r & 511;
        int b = bw >> 2, w = bw & 3;
        int st = s >> 6, l = s & 63;
        int t = (w * 8 + st + 4) & 31;            // roll(-SH) gather
        arow = A0 + ((size_t)((b * TT + t) * LLE + l) << 10);
    } else if (MODE == 1) {
        arow = g_O + ((size_t)(m0 + ra) << 10);
    }

    float acc[8][8];
    #pragma unroll
    for (int i = 0; i < 8; i++)
        #pragma unroll
        for (int j = 0; j < 8; j++) acc[i][j] = 0.f;

    const int nt = K >> 3;
    float4 pa = gemm_loadA<MODE>(arow, m0, ra, ka, 0);
    float4 pb = *(const float4*)(Bm + (size_t)kb * N + n0 + nb);

    int buf = 0;
    As[0][ka + 0][ra] = pa.x; As[0][ka + 1][ra] = pa.y;
    As[0][ka + 2][ra] = pa.z; As[0][ka + 3][ra] = pa.w;
    *(float4*)&Bs[0][kb][nb] = pb;
    __syncthreads();

    for (int t = 0; t < nt; t++) {
        if (t + 1 < nt) {
            int k0 = (t + 1) << 3;
            pa = gemm_loadA<MODE>(arow, m0, ra, ka, k0);
            pb = *(const float4*)(Bm + (size_t)(k0 + kb) * N + n0 + nb);
        }
        #pragma unroll
        for (int k = 0; k < 8; k++) {
            float4 a0 = *(const float4*)&As[buf][k][ty * 4];
            float4 a1 = *(const float4*)&As[buf][k][64 + ty * 4];
            float4 b0 = *(const float4*)&Bs[buf][k][tx * 4];
            float4 b1 = *(const float4*)&Bs[buf][k][64 + tx * 4];
            float av[8] = {a0.x, a0.y, a0.z, a0.w, a1.x, a1.y, a1.z, a1.w};
            float bv[8] = {b0.x, b0.y, b0.z, b0.w, b1.x, b1.y, b1.z, b1.w};
            #pragma unroll
            for (int i = 0; i < 8; i++)
                #pragma unroll
                for (int j = 0; j < 8; j++)
                    acc[i][j] = fmaf(av[i], bv[j], acc[i][j]);
        }
        if (t + 1 < nt) {
            buf ^= 1;
            As[buf][ka + 0][ra] = pa.x; As[buf][ka + 1][ra] = pa.y;
            As[buf][ka + 2][ra] = pa.z; As[buf][ka + 3][ra] = pa.w;
            *(float4*)&Bs[buf][kb][nb] = pb;
            __syncthreads();
        }
    }

    float* Cp;
    if (MODE == 0)      Cp = (which == 0) ? g_Q : (which == 1) ? g_K : g_V;
    else if (MODE == 1) Cp = g_feats + (size_t)which * BTLR * DD;
    else                Cp = g_G;

    #pragma unroll
    for (int iq = 0; iq < 2; iq++)
    #pragma unroll
    for (int ii = 0; ii < 4; ii++) {
        const int i = iq * 4 + ii;
        const int m = m0 + iq * 64 + ty * 4 + ii;
        int bw = m >> 9, s = m & 511;
        int b = bw >> 2, w = bw & 3;
        int st = s >> 6, l = s & 63;
        int tg = (w * 8 + st + 4) & 31;           // roll(+SH) scatter (same map)
        #pragma unroll
        for (int jq = 0; jq < 2; jq++) {
            const int n = n0 + jq * 64 + (tx << 2);
            float4 v;
            v.x = acc[i][jq * 4 + 0] + bias[n + 0];
            v.y = acc[i][jq * 4 + 1] + bias[n + 1];
            v.z = acc[i][jq * 4 + 2] + bias[n + 2];
            v.w = acc[i][jq * 4 + 3] + bias[n + 3];
            if (MODE == 0) {
                int h = n >> 6, d = n & 63;
                *(float4*)(Cp + (((size_t)(bw * HH + h) * SSQ + s) * HD + d)) = v;
            } else if (MODE == 1) {
                const float* rr = resid
                    + ((size_t)((b * TT + tg) * LLE + l) << 10) + n;
                float4 r4 = *(const float4*)rr;
                v.x += r4.x; v.y += r4.y; v.z += r4.z; v.w += r4.w;
                size_t fr = (size_t)(b * TLTOK + tg * LLE + l);
                *(float4*)(Cp + (fr << 10) + n) = v;
            } else {
                v.x = gelu_f(v.x); v.y = gelu_f(v.y);
                v.z = gelu_f(v.z); v.w = gelu_f(v.w);
                *(float4*)(Cp + (size_t)m * DG + n) = v;
            }
        }
    }
}

// ---------------------------------------------------------------------------
// RMS norm over head dim (64), one warp per row. scale folds HD^-0.5 into q.
// ---------------------------------------------------------------------------
__global__ __launch_bounds__(256) void rms_k(int which, const float* __restrict__ w,
                                             float scale)
{
    float* X = which ? g_K : g_Q;
    int row  = blockIdx.x * 8 + (threadIdx.x >> 5);
    int lane = threadIdx.x & 31;
    float* p = X + (size_t)row * HD;
    float x0 = p[lane], x1 = p[lane + 32];
    float ss = x0 * x0 + x1 * x1;
    #pragma unroll
    for (int m = 16; m; m >>= 1) ss += __shfl_xor_sync(0xffffffffu, ss, m);
    float rs = rsqrtf(ss * (1.0f / 64.0f) + 1e-6f) * scale;
    p[lane]      = x0 * rs * w[lane];
    p[lane + 32] = x1 * rs * w[lane + 32];
}

// ---------------------------------------------------------------------------
// Windowed attention with online softmax.
// Block: one (window*head, 32 q-rows). 256 threads as 16(tx: 4 keys / 4 out-
// dims) x 16(ty: 2 q-rows). K/V share a union smem buffer; bias is a scalar
// per (q-temporal, key-tile) since key tiles align with L=64.
// ---------------------------------------------------------------------------
__global__ __launch_bounds__(256) void attn_k(const float* __restrict__ rpb,
                                              int dummy)
{
    __shared__ float Qst[64][33];   // [d][q]
    __shared__ float KVs[64][65];   // [key][d] (K then V, reused)
    __shared__ float Pst[64][33];   // [key][q]

    const int tid = threadIdx.x;
    const int tx = tid & 15, ty = tid >> 4;
    const int bh = blockIdx.x;           // bw*16 + h
    const int q0 = blockIdx.y * 32;
    const int h  = bh & 15;
    const int tq = blockIdx.y >> 1;      // temporal coord of these q rows
    const int bw = bh >> 4;

    const float* Qb = g_Q + (size_t)bh * SSQ * HD;
    const float* Kb = g_K + (size_t)bh * SSQ * HD;
    const float* Vb = g_V + (size_t)bh * SSQ * HD;

    {   // load Q tile transposed
        int qi = tid >> 3;
        int dg = (tid & 7) * 8;
        #pragma unroll
        for (int u = 0; u < 2; u++) {
            float4 q4 = *(const float4*)(Qb + (size_t)(q0 + qi) * HD + dg + u * 4);
            Qst[dg + u * 4 + 0][qi] = q4.x;
            Qst[dg + u * 4 + 1][qi] = q4.y;
            Qst[dg + u * 4 + 2][qi] = q4.z;
            Qst[dg + u * 4 + 3][qi] = q4.w;
        }
    }

    float m_i[2] = {-1e30f, -1e30f};
    float l_i[2] = {0.f, 0.f};
    float oa[2][4] = {{0, 0, 0, 0}, {0, 0, 0, 0}};

    const int kk = tid >> 2;           // key row for loads (0..63)
    const int kd = (tid & 3) * 16;     // d offset for loads

    for (int kt = 0; kt < 8; kt++) {
        const float bias_s = rpb[(tq - kt + 7) * HH + h];

        __syncthreads();               // prev-iter V readers done (also Q ready)
        #pragma unroll
        for (int u = 0; u < 4; u++) {  // K tile
            float4 t4 = *(const float4*)(Kb + (size_t)(kt * 64 + kk) * HD + kd + u * 4);
            KVs[kk][kd + u * 4 + 0] = t4.x;
            KVs[kk][kd + u * 4 + 1] = t4.y;
            KVs[kk][kd + u * 4 + 2] = t4.z;
            KVs[kk][kd + u * 4 + 3] = t4.w;
        }
        __syncthreads();

        float sc[2][4] = {{0, 0, 0, 0}, {0, 0, 0, 0}};
        #pragma unroll 8
        for (int d = 0; d < 64; d++) {
            float a0 = Qst[d][ty * 2 + 0];
            float a1 = Qst[d][ty * 2 + 1];
            float b0 = KVs[tx * 4 + 0][d];
            float b1 = KVs[tx * 4 + 1][d];
            float b2 = KVs[tx * 4 + 2][d];
            float b3 = KVs[tx * 4 + 3][d];
            sc[0][0] = fmaf(a0, b0, sc[0][0]); sc[0][1] = fmaf(a0, b1, sc[0][1]);
            sc[0][2] = fmaf(a0, b2, sc[0][2]); sc[0][3] = fmaf(a0, b3, sc[0][3]);
            sc[1][0] = fmaf(a1, b0, sc[1][0]); sc[1][1] = fmaf(a1, b1, sc[1][1]);
            sc[1][2] = fmaf(a1, b2, sc[1][2]); sc[1][3] = fmaf(a1, b3, sc[1][3]);
        }
        __syncthreads();               // done reading K

        #pragma unroll
        for (int u = 0; u < 4; u++) {  // V tile (overwrites K)
            float4 t4 = *(const float4*)(Vb + (size_t)(kt * 64 + kk) * HD + kd + u * 4);
            KVs[kk][kd + u * 4 + 0] = t4.x;
            KVs[kk][kd + u * 4 + 1] = t4.y;
            KVs[kk][kd + u * 4 + 2] = t4.z;
            KVs[kk][kd + u * 4 + 3] = t4.w;
        }

        // online softmax update (row groups = 16 lanes sharing ty)
        #pragma unroll
        for (int i = 0; i < 2; i++) {
            float mx = fmaxf(fmaxf(sc[i][0], sc[i][1]), fmaxf(sc[i][2], sc[i][3]));
            mx += bias_s;
            #pragma unroll
            for (int msk = 8; msk; msk >>= 1)
                mx = fmaxf(mx, __shfl_xor_sync(0xffffffffu, mx, msk));
            float mn = fmaxf(m_i[i], mx);
            float p0 = __expf(sc[i][0] + bias_s - mn);
            float p1 = __expf(sc[i][1] + bias_s - mn);
            float p2 = __expf(sc[i][2] + bias_s - mn);
            float p3 = __expf(sc[i][3] + bias_s - mn);
            float rs = p0 + p1 + p2 + p3;
            #pragma unroll
            for (int msk = 8; msk; msk >>= 1)
                rs += __shfl_xor_sync(0xffffffffu, rs, msk);
            float fac = __expf(m_i[i] - mn);
            l_i[i] = l_i[i] * fac + rs;
            oa[i][0] *= fac; oa[i][1] *= fac; oa[i][2] *= fac; oa[i][3] *= fac;
            m_i[i] = mn;
            Pst[tx * 4 + 0][ty * 2 + i] = p0;
            Pst[tx * 4 + 1][ty * 2 + i] = p1;
            Pst[tx * 4 + 2][ty * 2 + i] = p2;
            Pst[tx * 4 + 3][ty * 2 + i] = p3;
        }
        __syncthreads();               // V + P visible

        #pragma unroll 4
        for (int k = 0; k < 64; k++) {
            float a0 = Pst[k][ty * 2 + 0];
            float a1 = Pst[k][ty * 2 + 1];
            float v0 = KVs[k][tx * 4 + 0];
            float v1 = KVs[k][tx * 4 + 1];
            float v2 = KVs[k][tx * 4 + 2];
            float v3 = KVs[k][tx * 4 + 3];
            oa[0][0] = fmaf(a0, v0, oa[0][0]); oa[0][1] = fmaf(a0, v1, oa[0][1]);
            oa[0][2] = fmaf(a0, v2, oa[0][2]); oa[0][3] = fmaf(a0, v3, oa[0][3]);
            oa[1][0] = fmaf(a1, v0, oa[1][0]); oa[1][1] = fmaf(a1, v1, oa[1][1]);
            oa[1][2] = fmaf(a1, v2, oa[1][2]); oa[1][3] = fmaf(a1, v3, oa[1][3]);
        }
    }

    #pragma unroll
    for (int i = 0; i < 2; i++) {
        float inv = 1.0f / l_i[i];
        float4 w4 = {oa[i][0] * inv, oa[i][1] * inv, oa[i][2] * inv, oa[i][3] * inv};
        *(float4*)(g_O + (size_t)(bw * SSQ + q0 + ty * 2 + i) * DD + h * HD + tx * 4) = w4;
    }
}

// ---------------------------------------------------------------------------
// Gate logits + softmax + fused output. One block per token row.
// ---------------------------------------------------------------------------
__global__ __launch_bounds__(256) void gate_fuse_k(const float* __restrict__ Wg2,
                                                   const float* __restrict__ bg2,
                                                   float* __restrict__ out)
{
    const int row = blockIdx.x;
    const int tid = threadIdx.x;
    const float* g = g_G + (size_t)row * DG;
    float s0 = 0.f, s1 = 0.f, s2 = 0.f;
    for (int k = tid; k < DG; k += 256) {
        float x = g[k];
        s0 = fmaf(x, Wg2[k * 3 + 0], s0);
        s1 = fmaf(x, Wg2[k * 3 + 1], s1);
        s2 = fmaf(x, Wg2[k * 3 + 2], s2);
    }
    #pragma unroll
    for (int m = 16; m; m >>= 1) {
        s0 += __shfl_xor_sync(0xffffffffu, s0, m);
        s1 += __shfl_xor_sync(0xffffffffu, s1, m);
        s2 += __shfl_xor_sync(0xffffffffu, s2, m);
    }
    __shared__ float red[3][8];
    __shared__ float gl[3];
    int wid = tid >> 5, lane = tid & 31;
    if (lane == 0) { red[0][wid] = s0; red[1][wid] = s1; red[2][wid] = s2; }
    __syncthreads();
    if (tid < 3) {
        float s = bg2[tid];
        #pragma unroll
        for (int w = 0; w < 8; w++) s += red[tid][w];
        gl[tid] = s;
    }
    __syncthreads();
    float a0 = gl[0], a1 = gl[1], a2 = gl[2];
    float mx = fmaxf(a0, fmaxf(a1, a2));
    float e0 = __expf(a0 - mx), e1 = __expf(a1 - mx), e2 = __expf(a2 - mx);
    float inv = 1.0f / (e0 + e1 + e2);
    e0 *= inv; e1 *= inv; e2 *= inv;

    const float4* f0 = (const float4*)(g_feats + ((size_t)0 * BTLR + row) * DD);
    const float4* f1 = (const float4*)(g_feats + ((size_t)1 * BTLR + row) * DD);
    const float4* f2 = (const float4*)(g_feats + ((size_t)2 * BTLR + row) * DD);
    float4* o4 = (float4*)(out + (size_t)row * DD);
    float4 v0 = f0[tid], v1 = f1[tid], v2 = f2[tid];
    float4 r;
    r.x = e0 * v0.x + e1 * v1.x + e2 * v2.x;
    r.y = e0 * v0.y + e1 * v1.y + e2 * v2.y;
    r.z = e0 * v0.z + e1 * v1.z + e2 * v2.z;
    r.w = e0 * v0.w + e1 * v1.w + e2 * v2.w;
    o4[tid] = r;
}

// ---------------------------------------------------------------------------
// Launch
// ---------------------------------------------------------------------------
extern "C" void kernel_launch(void* const* d_in, const int* in_sizes, int n_in,
                              void* d_out, int out_size)
{
    const float* audio = (const float*)d_in[0];
    const float* video = (const float*)d_in[1];
    const float* image = (const float*)d_in[2];
    const float* Wq    = (const float*)d_in[3];
    const float* Wk    = (const float*)d_in[4];
    const float* Wv    = (const float*)d_in[5];
    const float* Wp    = (const float*)d_in[6];
    const float* bq    = (const float*)d_in[7];
    const float* bk    = (const float*)d_in[8];
    const float* bv    = (const float*)d_in[9];
    const float* bp    = (const float*)d_in[10];
    const float* qn    = (const float*)d_in[11];
    const float* kn    = (const float*)d_in[12];
    const float* rpb   = (const float*)d_in[13];
    const float* Wg1   = (const float*)d_in[14];
    const float* bg1   = (const float*)d_in[15];
    const float* Wg2   = (const float*)d_in[16];
    const float* bg2   = (const float*)d_in[17];
    float* out = (float*)d_out;

    const float* qs[3] = {audio, video, image};
    const float* ks[3] = {video, audio, video};

    dim3 blk(256);
    dim3 gP(8, 32);   // N=1024, M=4096

    for (int j = 0; j < 3; j++) {
        size_t wo = (size_t)j * DD * DD;
        gemm_k<0><<<gP, blk>>>(qs[j], Wq + wo, bq + j * DD, nullptr, 0, DD, DD);
        gemm_k<0><<<gP, blk>>>(ks[j], Wk + wo, bk + j * DD, nullptr, 1, DD, DD);
        gemm_k<0><<<gP, blk>>>(ks[j], Wv + wo, bv + j * DD, nullptr, 2, DD, DD);
        rms_k<<<8192, 256>>>(0, qn + j * HD, 0.125f);   // fold HD^-0.5 into q
        rms_k<<<8192, 256>>>(1, kn + j * HD, 1.0f);
        attn_k<<<dim3(128, 16), blk>>>(rpb + j * 15 * HH, 0);
        gemm_k<1><<<gP, blk>>>(nullptr, Wp + wo, bp + j * DD, qs[j], j, DD, DD);
    }
    gemm_k<2><<<dim3(16, 32), blk>>>(nullptr, Wg1, bg1, nullptr, 0, K3D, DG);
    gate_fuse_k<<<BTLR, 256>>>(Wg2, bg2, out);
}